// round 5
// baseline (speedup 1.0000x reference)
#include <cuda_runtime.h>
#include <math.h>
#include <stdint.h>

// Problem constants (fixed by the reference)
#define Nn 100000
#define Ee 400000
#define Rr 4
#define Gg 64
#define INF 64
#define Hh 128
#define Cc 2

// ---------------- scratch (device globals; no allocation allowed) ----------
__device__ float g_h0  [(size_t)Nn * Hh];
__device__ float g_agg [(size_t)Nn * Hh];
__device__ float g_out1[(size_t)Nn * Hh];
__device__ float g_out2[(size_t)Nn * Hh];
__device__ float g_rsq_out[Rr * Nn];
__device__ float g_rsq_in [Rr * Nn];
__device__ float g_pool[Gg * Hh];
__device__ float g_cnt [Gg];
// transposed + tf32 hi/lo split weights: [(l*4+r)][hilo][n(128)][k(128)]
__device__ float g_wt   [2 * Rr * 2 * Hh * Hh];
// input weights: [hilo][n(128)][k(64)]
__device__ float g_wt_in[2 * Hh * INF];
__device__ float g_bsum [2 * Hh];   // per-layer sum of relation biases

// ---------------- tf32 helpers ----------------------------------------------
__device__ __forceinline__ float tf32_rna(float x) {
    uint32_t h;
    asm("cvt.rna.tf32.f32 %0, %1;" : "=r"(h) : "f"(x));
    return __uint_as_float(h);
}

// ---------------- prep kernels ----------------------------------------------
__global__ void wprep_kernel(const float* __restrict__ W1,
                             const float* __restrict__ W2,
                             const float* __restrict__ Win) {
    int i = blockIdx.x * blockDim.x + threadIdx.x;
    const int TL = Rr * Hh * Hh;  // 65536
    if (i < 2 * TL) {
        int l = i / TL, j = i % TL;
        int r = j >> 14;
        int k = (j >> 7) & 127;
        int n = j & 127;
        float w = (l == 0 ? W1 : W2)[j];
        float hi = tf32_rna(w);
        size_t base = (size_t)((l * Rr + r) * 2) * (Hh * Hh);
        g_wt[base + (size_t)n * Hh + k] = hi;
        g_wt[base + Hh * Hh + (size_t)n * Hh + k] = tf32_rna(w - hi);
    } else {
        int j = i - 2 * TL;
        if (j < INF * Hh) {
            int k = j >> 7, n = j & 127;
            float w = Win[j];
            float hi = tf32_rna(w);
            g_wt_in[n * INF + k] = hi;
            g_wt_in[Hh * INF + n * INF + k] = tf32_rna(w - hi);
        }
    }
}

__global__ void bsum_kernel(const float* __restrict__ b1,
                            const float* __restrict__ b2) {
    int j = threadIdx.x;
    if (j < Hh) {
        float s1 = 0.f, s2 = 0.f;
        for (int r = 0; r < Rr; ++r) { s1 += b1[r * Hh + j]; s2 += b2[r * Hh + j]; }
        g_bsum[j] = s1; g_bsum[Hh + j] = s2;
    }
}

// ---------------- degrees ---------------------------------------------------
__global__ void degree_kernel(const int* __restrict__ src, const int* __restrict__ dst) {
    int i = blockIdx.x * blockDim.x + threadIdx.x;
    if (i < Rr * Ee) {
        int r = i / Ee;
        atomicAdd(&g_rsq_out[r * Nn + src[i]], 1.f);
        atomicAdd(&g_rsq_in [r * Nn + dst[i]], 1.f);
    }
}
__global__ void rsq_kernel() {
    int i = blockIdx.x * blockDim.x + threadIdx.x;
    if (i < Rr * Nn) {
        g_rsq_out[i] = rsqrtf(fmaxf(g_rsq_out[i], 1.f));
        g_rsq_in [i] = rsqrtf(fmaxf(g_rsq_in [i], 1.f));
    }
}

// ---------------- edge scatter ----------------------------------------------
__device__ __forceinline__ void red_add_v4(float* p, float4 v) {
    asm volatile(
        "{\n\t.reg .u64 pg;\n\t"
        "cvta.to.global.u64 pg, %0;\n\t"
        "red.global.add.v4.f32 [pg], {%1,%2,%3,%4};\n\t}"
        :: "l"(p), "f"(v.x), "f"(v.y), "f"(v.z), "f"(v.w) : "memory");
}

template <int RELU_IN>
__global__ void scatter_kernel(const float* __restrict__ h,
                               const int*   __restrict__ src,
                               const int*   __restrict__ dst,
                               const float* __restrict__ rsq_out,
                               float*       __restrict__ agg) {
    int t = blockIdx.x * blockDim.x + threadIdx.x;
    int e = t >> 5;
    int lane = t & 31;
    if (e >= Ee) return;
    int s = __ldg(&src[e]);
    int d = __ldg(&dst[e]);
    float sc = __ldg(&rsq_out[s]);
    float4 v = *(const float4*)&h[(size_t)s * Hh + lane * 4];
    if (RELU_IN) {
        v.x = fmaxf(v.x, 0.f); v.y = fmaxf(v.y, 0.f);
        v.z = fmaxf(v.z, 0.f); v.w = fmaxf(v.w, 0.f);
    }
    v.x *= sc; v.y *= sc; v.z *= sc; v.w *= sc;
    red_add_v4(&agg[(size_t)d * Hh + lane * 4], v);
}

// ---------------- tf32 mma.sync GEMM (3xTF32 emulation, explicit rna) --------
// C[row,128] (+)= rowscale[row] * (A[row,0:K] @ W^T) + bias, near-fp32 exact.
// Virtual K'=3K: pass0 = rna(A) x W_hi, pass1 = rna(A - rna(A)) x W_hi,
// pass2 = rna(A) x W_lo. Missing lo*lo term is O(eps^2) ~ 2e-7.
// All operands explicitly tf32-rounded (HW truncates raw f32 bits!).
// Tile: 128(M) x 128(N), BK=32, 256 threads = 8 warps in 4(M)x2(N).
#define SMS 36   // padded smem stride (floats)

__device__ __forceinline__ void mma8(float* c, const uint32_t* a,
                                     uint32_t b0, uint32_t b1) {
    asm volatile(
        "mma.sync.aligned.m16n8k8.row.col.f32.tf32.tf32.f32 "
        "{%0,%1,%2,%3}, {%4,%5,%6,%7}, {%8,%9}, {%0,%1,%2,%3};"
        : "+f"(c[0]), "+f"(c[1]), "+f"(c[2]), "+f"(c[3])
        : "r"(a[0]), "r"(a[1]), "r"(a[2]), "r"(a[3]), "r"(b0), "r"(b1));
}

__global__ void __launch_bounds__(256)
mma_gemm_kernel(const float* __restrict__ A, int K,
                const float* __restrict__ Wt,       // [2][128][K] hi then lo (tf32)
                const float* __restrict__ bias,     // nullable (128)
                const float* __restrict__ rowscale, // nullable (n)
                float* __restrict__ C,
                int n, int accum, int relu) {
    extern __shared__ float sm[];
    float* As = sm;                     // [2][128*SMS]
    float* Bs = sm + 2 * 128 * SMS;     // [2][128*SMS]

    const int tid  = threadIdx.x;
    const int lane = tid & 31, warp = tid >> 5;
    const int wm = warp >> 1, wn = warp & 1;
    const int g = lane >> 2, t = lane & 3;
    const int row0 = blockIdx.x * 128;
    const int kdiv = K >> 5;       // chunks per pass
    const int NC = 3 * kdiv;

    // staging: thread covers row sr, 4 float4s at cols sc..sc+15
    const int sr = tid >> 1;
    const int sc = (tid & 1) * 16;
    const int grow_s = row0 + sr;

    float acc[2][8][4];
#pragma unroll
    for (int mf = 0; mf < 2; ++mf)
#pragma unroll
        for (int nf = 0; nf < 8; ++nf)
#pragma unroll
            for (int q = 0; q < 4; ++q) acc[mf][nf][q] = 0.f;

    float4 ra[4], rb[4];
    // ---- load chunk 0 (sel=0: rna(A), W_hi, kk0=0)
#pragma unroll
    for (int q = 0; q < 4; ++q) {
        int col = sc + q * 4;
        ra[q] = make_float4(0.f, 0.f, 0.f, 0.f);
        if (grow_s < n) ra[q] = *(const float4*)(A + (size_t)grow_s * K + col);
        ra[q].x = tf32_rna(ra[q].x); ra[q].y = tf32_rna(ra[q].y);
        ra[q].z = tf32_rna(ra[q].z); ra[q].w = tf32_rna(ra[q].w);
        rb[q] = *(const float4*)(Wt + (size_t)sr * K + col);
    }
#pragma unroll
    for (int q = 0; q < 4; ++q) {
        *(float4*)(As + sr * SMS + sc + q * 4) = ra[q];
        *(float4*)(Bs + sr * SMS + sc + q * 4) = rb[q];
    }
    __syncthreads();

    for (int c = 0; c < NC; ++c) {
        const int buf = c & 1;
        const bool pf = (c + 1) < NC;
        // prefetch chunk c+1 into registers
        if (pf) {
            int c1  = c + 1;
            int sel = c1 / kdiv;                 // 0: Ahi*Whi 1: Alo*Whi 2: Ahi*Wlo
            int kk0 = (c1 - sel * kdiv) * 32;
            const float* bp = Wt + (sel == 2 ? (size_t)128 * K : 0);
#pragma unroll
            for (int q = 0; q < 4; ++q) {
                int col = kk0 + sc + q * 4;
                float4 v = make_float4(0.f, 0.f, 0.f, 0.f);
                if (grow_s < n) v = *(const float4*)(A + (size_t)grow_s * K + col);
                if (sel == 1) {
                    v.x = tf32_rna(v.x - tf32_rna(v.x));
                    v.y = tf32_rna(v.y - tf32_rna(v.y));
                    v.z = tf32_rna(v.z - tf32_rna(v.z));
                    v.w = tf32_rna(v.w - tf32_rna(v.w));
                } else {
                    v.x = tf32_rna(v.x); v.y = tf32_rna(v.y);
                    v.z = tf32_rna(v.z); v.w = tf32_rna(v.w);
                }
                ra[q] = v;
                rb[q] = *(const float4*)(bp + (size_t)sr * K + col);
            }
        }
        // MMA on current buffer
        const float* a_s = As + buf * 128 * SMS;
        const float* b_s = Bs + buf * 128 * SMS;
#pragma unroll
        for (int ks = 0; ks < 4; ++ks) {
            const int kk = ks * 8;
            uint32_t afr[2][4];
#pragma unroll
            for (int mf = 0; mf < 2; ++mf) {
                int r_ = wm * 32 + mf * 16 + g;
                afr[mf][0] = __float_as_uint(a_s[(r_    ) * SMS + kk + t    ]);
                afr[mf][1] = __float_as_uint(a_s[(r_ + 8) * SMS + kk + t    ]);
                afr[mf][2] = __float_as_uint(a_s[(r_    ) * SMS + kk + t + 4]);
                afr[mf][3] = __float_as_uint(a_s[(r_ + 8) * SMS + kk + t + 4]);
            }
#pragma unroll
            for (int nf = 0; nf < 8; ++nf) {
                int nr = wn * 64 + nf * 8 + g;
                uint32_t b0 = __float_as_uint(b_s[nr * SMS + kk + t    ]);
                uint32_t b1 = __float_as_uint(b_s[nr * SMS + kk + t + 4]);
                mma8(acc[0][nf], afr[0], b0, b1);
                mma8(acc[1][nf], afr[1], b0, b1);
            }
        }
        // publish prefetched chunk
        if (pf) {
            __syncthreads();
            float* a_d = As + ((c + 1) & 1) * 128 * SMS;
            float* b_d = Bs + ((c + 1) & 1) * 128 * SMS;
#pragma unroll
            for (int q = 0; q < 4; ++q) {
                *(float4*)(a_d + sr * SMS + sc + q * 4) = ra[q];
                *(float4*)(b_d + sr * SMS + sc + q * 4) = rb[q];
            }
            __syncthreads();
        }
    }

    // ---- epilogue
#pragma unroll
    for (int mf = 0; mf < 2; ++mf) {
#pragma unroll
        for (int half = 0; half < 2; ++half) {
            int grow = row0 + wm * 32 + mf * 16 + g + half * 8;
            if (grow >= n) continue;
            float rs = rowscale ? __ldg(&rowscale[grow]) : 1.f;
            float* crow = C + (size_t)grow * 128;
#pragma unroll
            for (int nf = 0; nf < 8; ++nf) {
                int col = wn * 64 + nf * 8 + 2 * t;
                float v0 = acc[mf][nf][half * 2 + 0] * rs;
                float v1 = acc[mf][nf][half * 2 + 1] * rs;
                if (bias) { v0 += bias[col]; v1 += bias[col + 1]; }
                if (accum) {
                    float2 o = *(float2*)(crow + col);
                    v0 += o.x; v1 += o.y;
                }
                if (relu) { v0 = fmaxf(v0, 0.f); v1 = fmaxf(v1, 0.f); }
                float2 v; v.x = v0; v.y = v1;
                *(float2*)(crow + col) = v;
            }
        }
    }
}

// ---------------- pooling ----------------------------------------------------
__global__ void count_kernel(const int* __restrict__ gid) {
    int i = blockIdx.x * blockDim.x + threadIdx.x;
    if (i < Nn) atomicAdd(&g_cnt[gid[i]], 1.f);
}
__global__ void pool_kernel(const float* __restrict__ h, const int* __restrict__ gid) {
    int t = blockIdx.x * blockDim.x + threadIdx.x;
    int node = t >> 5;
    int lane = t & 31;
    if (node >= Nn) return;
    int g = __ldg(&gid[node]);
    float4 v = *(const float4*)&h[(size_t)node * Hh + lane * 4];
    red_add_v4(&g_pool[g * Hh + lane * 4], v);
}

// ---------------- MLP head (single block) -------------------------------------
__global__ void mlp_kernel(const float* __restrict__ Wm1, const float* __restrict__ bm1,
                           const float* __restrict__ Wm2, const float* __restrict__ bm2,
                           const float* __restrict__ Wm3, const float* __restrict__ bm3,
                           float* __restrict__ out) {
    __shared__ float z[Gg * Hh];
    int tid = threadIdx.x;   // 256
    for (int i = tid; i < Gg * Hh; i += 256)
        z[i] = g_pool[i] / fmaxf(g_cnt[i >> 7], 1.f);
    __syncthreads();
    float r1[32];
#pragma unroll
    for (int t = 0; t < 32; ++t) {
        int o = tid + t * 256, g = o >> 7, j = o & 127;
        float s = bm1[j];
        for (int k = 0; k < Hh; ++k) s += z[(g << 7) + k] * Wm1[k * Hh + j];
        r1[t] = fmaxf(s, 0.f);
    }
    __syncthreads();
#pragma unroll
    for (int t = 0; t < 32; ++t) z[tid + t * 256] = r1[t];
    __syncthreads();
#pragma unroll
    for (int t = 0; t < 32; ++t) {
        int o = tid + t * 256, g = o >> 7, j = o & 127;
        float s = bm2[j];
        for (int k = 0; k < Hh; ++k) s += z[(g << 7) + k] * Wm2[k * Hh + j];
        r1[t] = fmaxf(s, 0.f);
    }
    __syncthreads();
#pragma unroll
    for (int t = 0; t < 32; ++t) z[tid + t * 256] = r1[t];
    __syncthreads();
    if (tid < Gg * Cc) {
        int g = tid >> 1, c = tid & 1;
        float s = bm3[c];
        for (int k = 0; k < Hh; ++k) s += z[(g << 7) + k] * Wm3[k * Cc + c];
        out[tid] = s;
    }
}

// ---------------- launch -------------------------------------------------------
static float* sym(const void* s) {
    void* p = nullptr;
    cudaGetSymbolAddress(&p, s);
    return (float*)p;
}

extern "C" void kernel_launch(void* const* d_in, const int* in_sizes, int n_in,
                              void* d_out, int out_size) {
    const float* x    = (const float*)d_in[0];
    const int*   src  = (const int*)  d_in[1];
    const int*   dst  = (const int*)  d_in[2];
    const int*   gid  = (const int*)  d_in[3];
    const float* W_in = (const float*)d_in[4];
    const float* b_in = (const float*)d_in[5];
    const float* W1   = (const float*)d_in[6];
    const float* b1   = (const float*)d_in[7];
    const float* W2   = (const float*)d_in[8];
    const float* b2   = (const float*)d_in[9];
    const float* Wm1  = (const float*)d_in[10];
    const float* bm1  = (const float*)d_in[11];
    const float* Wm2  = (const float*)d_in[12];
    const float* bm2  = (const float*)d_in[13];
    const float* Wm3  = (const float*)d_in[14];
    const float* bm3  = (const float*)d_in[15];
    float* out = (float*)d_out;

    float* p_h0   = sym(g_h0);
    float* p_agg  = sym(g_agg);
    float* p_out1 = sym(g_out1);
    float* p_out2 = sym(g_out2);
    float* p_rso  = sym(g_rsq_out);
    float* p_rsi  = sym(g_rsq_in);
    float* p_pool = sym(g_pool);
    float* p_cnt  = sym(g_cnt);
    float* p_wt   = sym(g_wt);
    float* p_wtin = sym(g_wt_in);
    float* p_bsum = sym(g_bsum);

    const int TB = 256;
    const int gemm_blocks = (Nn + 127) / 128;      // 782
    const int scat_blocks = (Ee * 32 + TB - 1) / TB;
    const int smem_gemm = 4 * 128 * SMS * 4;       // 73728 bytes

    cudaFuncSetAttribute(mma_gemm_kernel,
                         cudaFuncAttributeMaxDynamicSharedMemorySize, smem_gemm);

    // degrees -> rsqrt
    cudaMemsetAsync(p_rso, 0, (size_t)Rr * Nn * sizeof(float));
    cudaMemsetAsync(p_rsi, 0, (size_t)Rr * Nn * sizeof(float));
    degree_kernel<<<(Rr * Ee + TB - 1) / TB, TB>>>(src, dst);
    rsq_kernel<<<(Rr * Nn + TB - 1) / TB, TB>>>();

    // weight prep (transpose + tf32 hi/lo split) + bias sums
    wprep_kernel<<<(2 * Rr * Hh * Hh + INF * Hh + TB - 1) / TB, TB>>>(W1, W2, W_in);
    bsum_kernel<<<1, 128>>>(b1, b2);

    // h0 = relu(x @ W_in + b_in)
    mma_gemm_kernel<<<gemm_blocks, 256, smem_gemm>>>(
        x, INF, p_wtin, b_in, nullptr, p_h0, Nn, 0, 1);

    // layer 1
    for (int r = 0; r < Rr; ++r) {
        cudaMemsetAsync(p_agg, 0, (size_t)Nn * Hh * sizeof(float));
        scatter_kernel<0><<<scat_blocks, TB>>>(p_h0, src + r * Ee, dst + r * Ee,
                                               p_rso + r * Nn, p_agg);
        mma_gemm_kernel<<<gemm_blocks, 256, smem_gemm>>>(
            p_agg, Hh, p_wt + (size_t)(0 * Rr + r) * 2 * Hh * Hh,
            r == 0 ? p_bsum : nullptr, p_rsi + r * Nn, p_out1, Nn, r > 0, 0);
    }

    // layer 2 (ReLU of out1 fused into the gather)
    for (int r = 0; r < Rr; ++r) {
        cudaMemsetAsync(p_agg, 0, (size_t)Nn * Hh * sizeof(float));
        scatter_kernel<1><<<scat_blocks, TB>>>(p_out1, src + r * Ee, dst + r * Ee,
                                               p_rso + r * Nn, p_agg);
        mma_gemm_kernel<<<gemm_blocks, 256, smem_gemm>>>(
            p_agg, Hh, p_wt + (size_t)(1 * Rr + r) * 2 * Hh * Hh,
            r == 0 ? p_bsum + Hh : nullptr, p_rsi + r * Nn, p_out2, Nn, r > 0, 0);
    }

    // per-graph mean pool
    cudaMemsetAsync(p_pool, 0, (size_t)Gg * Hh * sizeof(float));
    cudaMemsetAsync(p_cnt, 0, (size_t)Gg * sizeof(float));
    count_kernel<<<(Nn + TB - 1) / TB, TB>>>(gid);
    pool_kernel<<<(Nn * 32 + TB - 1) / TB, TB>>>(p_out2, gid);

    // MLP head
    mlp_kernel<<<1, TB>>>(Wm1, bm1, Wm2, bm2, Wm3, bm3, out);
}